// round 14
// baseline (speedup 1.0000x reference)
#include <cuda_runtime.h>
#include <cstdint>

// Shift_7292854469289  — out[b,c,h,w] = x[b,c, srcH[h], srcW[w]]
// srcH[h] = clamp(h + trunc(ypos[h]*stride), 0, H-1)
// srcW[w] = clamp(w + trunc(xpos[w]*stride), 0, W-1)
// B=16, C=64, H=W=256, fp32.
// FINAL — converged, reproduced 3x: 70.1us total / ~65us kernel, rel_err 0.
//   Register-only index math, BC_PER=4, 16B/lane loads+stores, plain STG.
// At the HBM mixed r/w roofline: ~394MB DRAM traffic (268MB compulsory write
// + ~126MB read, L2 dedups duplicate srcH rows) @ 6.07 TB/s = 64.9us == measured.
// Bracketed and rejected: width 4/32B, BC 2/8/16, smem tables, stcs,
// L2 evict_last/first policies, LDG.256, launch fusion, occupancy 63-87%.

#define H_ 256
#define W_ 256
#define W4_ 64                 // W/4
#define IMG4 (H_ * W4_)        // float4 elements per (b,c) plane
#define BC_PER 4               // bc planes per thread (measured optimum)

__global__ void __launch_bounds__(256) shift_reg4_kernel(
    const float4* __restrict__ x4,
    const float4* __restrict__ xpos4,
    const float*  __restrict__ ypos,
    const int*    __restrict__ stride_p,
    float4*       __restrict__ out4)
{
    unsigned int tid = blockIdx.x * 256u + threadIdx.x; // 256(bcg) x 256(h) x 64(w4)
    int w4  = tid & 63;
    int h   = (tid >> 6) & 255;
    unsigned int bcg = tid >> 14;               // 0..255
    unsigned int bc0 = bcg * BC_PER;

    const int stride = *stride_p;               // L2/L1-resident scalar

    // ---- index math entirely in registers ----
    // trunc toward zero == C float->int cast (matches Python int())
    int srcH = min(max(h + (int)(ypos[h] * (float)stride), 0), H_ - 1);

    float4 xp = __ldg(xpos4 + w4);              // xpos[4w4 .. 4w4+3]
    int w0  = w4 << 2;
    int sw0 = min(max(w0     + (int)(xp.x * (float)stride), 0), W_ - 1);
    int sw1 = min(max(w0 + 1 + (int)(xp.y * (float)stride), 0), W_ - 1);
    int sw2 = min(max(w0 + 2 + (int)(xp.z * (float)stride), 0), W_ - 1);
    int sw3 = min(max(w0 + 3 + (int)(xp.w * (float)stride), 0), W_ - 1);

    bool vec = ((sw0 & 3) == 0) & (sw1 == sw0 + 1) & (sw2 == sw0 + 2)
                                & (sw3 == sw0 + 3);

    size_t in_row  = (size_t)srcH * W4_;
    size_t out_idx = (size_t)bc0 * IMG4 + (size_t)h * W4_ + w4;

    if (vec) {
        size_t in_idx = (size_t)bc0 * IMG4 + in_row + (sw0 >> 2);
        float4 v0 = __ldg(x4 + in_idx);
        float4 v1 = __ldg(x4 + in_idx + IMG4);
        float4 v2 = __ldg(x4 + in_idx + 2 * IMG4);
        float4 v3 = __ldg(x4 + in_idx + 3 * IMG4);
        out4[out_idx]            = v0;
        out4[out_idx + IMG4]     = v1;
        out4[out_idx + 2 * IMG4] = v2;
        out4[out_idx + 3 * IMG4] = v3;
    } else {
        const float* xf = (const float*)x4;
        #pragma unroll
        for (int i = 0; i < BC_PER; i++) {
            const float* row = xf + ((size_t)(bc0 + i) * IMG4 + in_row) * 4;
            float4 v;
            v.x = __ldg(row + sw0);
            v.y = __ldg(row + sw1);
            v.z = __ldg(row + sw2);
            v.w = __ldg(row + sw3);
            out4[out_idx + (size_t)i * IMG4] = v;
        }
    }
}

// Generic fallback (any H, W): one thread per element.
__global__ void shift_kernel_generic(
    const float* __restrict__ x,
    const float* __restrict__ xpos,
    const float* __restrict__ ypos,
    const int*   __restrict__ stride_p,
    float*       __restrict__ out,
    int H, int W, long long total)
{
    const int stride = *stride_p;
    long long i = (long long)blockIdx.x * blockDim.x + threadIdx.x;
    if (i >= total) return;
    int w = (int)(i % W);
    long long r = i / W;
    int h = (int)(r % H);
    long long bc = r / H;

    int srcH = min(max(h + (int)(ypos[h] * (float)stride), 0), H - 1);
    int srcW = min(max(w + (int)(xpos[w] * (float)stride), 0), W - 1);
    out[i] = x[(bc * H + srcH) * (long long)W + srcW];
}

extern "C" void kernel_launch(void* const* d_in, const int* in_sizes, int n_in,
                              void* d_out, int out_size)
{
    const float* x      = (const float*)d_in[0];
    const float* xpos   = (const float*)d_in[1];
    const float* ypos   = (const float*)d_in[2];
    const int*   stride = (const int*)d_in[3];
    float* out = (float*)d_out;

    int W = in_sizes[1];   // xpos has W elements
    int H = in_sizes[2];   // ypos has H elements

    long long total = out_size;
    long long bc_total = total / ((long long)H * W);   // B*C

    if (H == 256 && W == 256 && bc_total == 1024 &&
        ((((uintptr_t)xpos) & 15) == 0)) {
        // threads = (1024/4 bc groups) * 256 h * 64 w4 = 4,194,304 -> 16384 blocks
        shift_reg4_kernel<<<16384, 256>>>((const float4*)x, (const float4*)xpos,
                                          ypos, stride, (float4*)out);
    } else {
        int threads = 256;
        long long blocks = (total + threads - 1) / threads;
        shift_kernel_generic<<<(unsigned int)blocks, threads>>>(
            x, xpos, ypos, stride, out, H, W, total);
    }
}

// round 15
// speedup vs baseline: 1.0219x; 1.0219x over previous
#include <cuda_runtime.h>
#include <cstdint>

// Shift_7292854469289  — out[b,c,h,w] = x[b,c, srcH[h], srcW[w]]
// srcH[h] = clamp(h + trunc(ypos[h]*stride), 0, H-1)
// srcW[w] = clamp(w + trunc(xpos[w]*stride), 0, W-1)
// B=16, C=64, H=W=256, fp32.
// FINAL — converged, reproduced 4x: ~65us kernel (70.1us best total), rel_err 0.
//   Register-only index math, BC_PER=4, 16B/lane loads+stores, plain STG.
// At the HBM mixed r/w roofline: ~394MB DRAM traffic (268MB compulsory write
// + ~126MB read; x partially L2-resident across replays, below even the
// single-pass unique-row read minimum) @ ~6.07 TB/s = 64.9us == measured.
// Bracketed and rejected: width 4/32B, BC 2/8/16, smem tables, stcs,
// L2 evict_last/first policies, LDG.256, launch fusion, occupancy 63-87%.

#define H_ 256
#define W_ 256
#define W4_ 64                 // W/4
#define IMG4 (H_ * W4_)        // float4 elements per (b,c) plane
#define BC_PER 4               // bc planes per thread (measured optimum)

__global__ void __launch_bounds__(256) shift_reg4_kernel(
    const float4* __restrict__ x4,
    const float4* __restrict__ xpos4,
    const float*  __restrict__ ypos,
    const int*    __restrict__ stride_p,
    float4*       __restrict__ out4)
{
    unsigned int tid = blockIdx.x * 256u + threadIdx.x; // 256(bcg) x 256(h) x 64(w4)
    int w4  = tid & 63;
    int h   = (tid >> 6) & 255;
    unsigned int bcg = tid >> 14;               // 0..255
    unsigned int bc0 = bcg * BC_PER;

    const int stride = *stride_p;               // L2/L1-resident scalar

    // ---- index math entirely in registers ----
    // trunc toward zero == C float->int cast (matches Python int())
    int srcH = min(max(h + (int)(ypos[h] * (float)stride), 0), H_ - 1);

    float4 xp = __ldg(xpos4 + w4);              // xpos[4w4 .. 4w4+3]
    int w0  = w4 << 2;
    int sw0 = min(max(w0     + (int)(xp.x * (float)stride), 0), W_ - 1);
    int sw1 = min(max(w0 + 1 + (int)(xp.y * (float)stride), 0), W_ - 1);
    int sw2 = min(max(w0 + 2 + (int)(xp.z * (float)stride), 0), W_ - 1);
    int sw3 = min(max(w0 + 3 + (int)(xp.w * (float)stride), 0), W_ - 1);

    bool vec = ((sw0 & 3) == 0) & (sw1 == sw0 + 1) & (sw2 == sw0 + 2)
                                & (sw3 == sw0 + 3);

    size_t in_row  = (size_t)srcH * W4_;
    size_t out_idx = (size_t)bc0 * IMG4 + (size_t)h * W4_ + w4;

    if (vec) {
        size_t in_idx = (size_t)bc0 * IMG4 + in_row + (sw0 >> 2);
        float4 v0 = __ldg(x4 + in_idx);
        float4 v1 = __ldg(x4 + in_idx + IMG4);
        float4 v2 = __ldg(x4 + in_idx + 2 * IMG4);
        float4 v3 = __ldg(x4 + in_idx + 3 * IMG4);
        out4[out_idx]            = v0;
        out4[out_idx + IMG4]     = v1;
        out4[out_idx + 2 * IMG4] = v2;
        out4[out_idx + 3 * IMG4] = v3;
    } else {
        const float* xf = (const float*)x4;
        #pragma unroll
        for (int i = 0; i < BC_PER; i++) {
            const float* row = xf + ((size_t)(bc0 + i) * IMG4 + in_row) * 4;
            float4 v;
            v.x = __ldg(row + sw0);
            v.y = __ldg(row + sw1);
            v.z = __ldg(row + sw2);
            v.w = __ldg(row + sw3);
            out4[out_idx + (size_t)i * IMG4] = v;
        }
    }
}

// Generic fallback (any H, W): one thread per element.
__global__ void shift_kernel_generic(
    const float* __restrict__ x,
    const float* __restrict__ xpos,
    const float* __restrict__ ypos,
    const int*   __restrict__ stride_p,
    float*       __restrict__ out,
    int H, int W, long long total)
{
    const int stride = *stride_p;
    long long i = (long long)blockIdx.x * blockDim.x + threadIdx.x;
    if (i >= total) return;
    int w = (int)(i % W);
    long long r = i / W;
    int h = (int)(r % H);
    long long bc = r / H;

    int srcH = min(max(h + (int)(ypos[h] * (float)stride), 0), H - 1);
    int srcW = min(max(w + (int)(xpos[w] * (float)stride), 0), W - 1);
    out[i] = x[(bc * H + srcH) * (long long)W + srcW];
}

extern "C" void kernel_launch(void* const* d_in, const int* in_sizes, int n_in,
                              void* d_out, int out_size)
{
    const float* x      = (const float*)d_in[0];
    const float* xpos   = (const float*)d_in[1];
    const float* ypos   = (const float*)d_in[2];
    const int*   stride = (const int*)d_in[3];
    float* out = (float*)d_out;

    int W = in_sizes[1];   // xpos has W elements
    int H = in_sizes[2];   // ypos has H elements

    long long total = out_size;
    long long bc_total = total / ((long long)H * W);   // B*C

    if (H == 256 && W == 256 && bc_total == 1024 &&
        ((((uintptr_t)xpos) & 15) == 0)) {
        // threads = (1024/4 bc groups) * 256 h * 64 w4 = 4,194,304 -> 16384 blocks
        shift_reg4_kernel<<<16384, 256>>>((const float4*)x, (const float4*)xpos,
                                          ypos, stride, (float4*)out);
    } else {
        int threads = 256;
        long long blocks = (total + threads - 1) / threads;
        shift_kernel_generic<<<(unsigned int)blocks, threads>>>(
            x, xpos, ypos, stride, out, H, W, total);
    }
}